// round 1
// baseline (speedup 1.0000x reference)
#include <cuda_runtime.h>
#include <cstddef>

#define N_USERS 50000
#define N_ENT   100000
#define N_TOT   150000
#define D       64

// Scratch: transformed embeddings y = concat(user,entity) @ W, plus softmax denominator.
__device__ __align__(256) float g_y[(size_t)N_TOT * D];
__device__ float g_Z;

// ---------------------------------------------------------------------------
// Pass 1: y = x @ W  (x = gather of the two tables). Also zeroes g_Z.
// Block = 256 threads -> 16 rows per iteration, 16 threads (4 cols each) per row.
// ---------------------------------------------------------------------------
__global__ void __launch_bounds__(256) build_y_kernel(
    const int* __restrict__ uidx, const int* __restrict__ iidx,
    const float* __restrict__ ut, const float* __restrict__ et,
    const float* __restrict__ W)
{
    __shared__ float Ws[64 * 64];
    __shared__ float xs[16][68];   // pad 68 (mult of 4): float4 stores OK, LDS conflict-light

    if (blockIdx.x == 0 && threadIdx.x == 0) g_Z = 0.0f;

    const int tid = threadIdx.x;
    for (int i = tid; i < 1024; i += 256)
        ((float4*)Ws)[i] = ((const float4*)W)[i];
    __syncthreads();

    const int row_l = tid >> 4;   // 0..15
    const int j     = tid & 15;   // 0..15 -> cols [4j, 4j+4)
    const int ntiles = N_TOT / 16;

    for (int tile = blockIdx.x; tile < ntiles; tile += gridDim.x) {
        const int row0 = tile * 16;
        // cooperative load: 16 rows x 64 floats
        {
            const int r = row0 + row_l;
            const float* xrow;
            if (r < N_USERS) xrow = ut + (size_t)__ldg(uidx + r) * D;
            else             xrow = et + (size_t)__ldg(iidx + (r - N_USERS)) * D;
            float4 v = ((const float4*)xrow)[j];
            *(float4*)&xs[row_l][j * 4] = v;
        }
        __syncthreads();

        float4 acc = make_float4(0.f, 0.f, 0.f, 0.f);
        #pragma unroll 8
        for (int k = 0; k < 64; k++) {
            const float xv = xs[row_l][k];
            const float4 w4 = *(const float4*)&Ws[k * 64 + j * 4];
            acc.x += xv * w4.x; acc.y += xv * w4.y;
            acc.z += xv * w4.z; acc.w += xv * w4.w;
        }
        ((float4*)(g_y + (size_t)(row0 + row_l) * D))[j] = acc;
        __syncthreads();
    }
}

// ---------------------------------------------------------------------------
// Pass 2 (fused): per edge -> dot, leaky_relu, exp; scatter exp(l)*y[src] into
// out[dst] via vectorized red.global; accumulate Z. 16 lanes per edge.
// ---------------------------------------------------------------------------
__global__ void __launch_bounds__(256) edge_kernel(
    const int* __restrict__ ei, int E, float* __restrict__ out)
{
    const int lane = threadIdx.x & 31;
    const int li   = lane & 15;                                  // lane-in-group
    const int gid  = (blockIdx.x * blockDim.x + threadIdx.x) >> 4;
    const int ng   = (gridDim.x * blockDim.x) >> 4;

    float zloc = 0.0f;

    for (int e = gid; e < E; e += ng) {
        const int src = __ldg(ei + e);        // edge_index[0, e]
        const int dst = __ldg(ei + E + e);    // edge_index[1, e]

        const float4 ys = *(const float4*)(g_y + (size_t)src * D + li * 4);
        const float4 yd = *(const float4*)(g_y + (size_t)dst * D + li * 4);

        float d = ys.x * yd.x + ys.y * yd.y + ys.z * yd.z + ys.w * yd.w;
        d += __shfl_xor_sync(0xffffffffu, d, 8);
        d += __shfl_xor_sync(0xffffffffu, d, 4);
        d += __shfl_xor_sync(0xffffffffu, d, 2);
        d += __shfl_xor_sync(0xffffffffu, d, 1);   // all 16 lanes of group hold dot

        const float l = d >= 0.f ? d : 0.2f * d;   // leaky_relu(0.2)
        const float p = __expf(l);                 // logits are O(1): no max-shift needed

        if (li == 0) zloc += p;

        float* dp = out + (size_t)dst * D + li * 4;
        asm volatile("red.global.add.v4.f32 [%0], {%1,%2,%3,%4};"
                     :: "l"(dp), "f"(p * ys.x), "f"(p * ys.y),
                        "f"(p * ys.z), "f"(p * ys.w)
                     : "memory");
    }

    // block-reduce zloc -> one atomic per block
    #pragma unroll
    for (int o = 16; o > 0; o >>= 1) zloc += __shfl_xor_sync(0xffffffffu, zloc, o);
    __shared__ float sz[8];
    if (lane == 0) sz[threadIdx.x >> 5] = zloc;
    __syncthreads();
    if (threadIdx.x == 0) {
        float s = 0.f;
        #pragma unroll
        for (int w = 0; w < 8; w++) s += sz[w];
        atomicAdd(&g_Z, s);
    }
}

// ---------------------------------------------------------------------------
// Pass 3: out = relu(out) / Z   (relu(a/Z) == relu(a)/Z since Z > 0)
// ---------------------------------------------------------------------------
__global__ void __launch_bounds__(256) finalize_kernel(float* __restrict__ out, int n)
{
    const float invZ = 1.0f / g_Z;
    const int n4 = n >> 2;
    float4* o4 = (float4*)out;
    const int st = gridDim.x * blockDim.x;
    for (int i = blockIdx.x * blockDim.x + threadIdx.x; i < n4; i += st) {
        float4 v = o4[i];
        v.x = v.x > 0.f ? v.x * invZ : 0.f;
        v.y = v.y > 0.f ? v.y * invZ : 0.f;
        v.z = v.z > 0.f ? v.z * invZ : 0.f;
        v.w = v.w > 0.f ? v.w * invZ : 0.f;
        o4[i] = v;
    }
    // scalar tail (n is 9.6M, divisible by 4 — this is just belt & suspenders)
    for (int i = (n4 << 2) + blockIdx.x * blockDim.x + threadIdx.x; i < n; i += st) {
        float v = out[i];
        out[i] = v > 0.f ? v * invZ : 0.f;
    }
}

// ---------------------------------------------------------------------------
// Inputs (metadata order):
//  0 user_indices[50000] i32      1 item_indices[100000] i32
//  2 edge_index_ui[2,1.5M] i32    3 edge_index_kg (DEAD)  4 edge_type_kg (DEAD)
//  5 user_table[50000,64] f32     6 entity_table[100000,64] f32
//  7 W[64,64] f32                 8 W_r (DEAD)
// Output: concat(relu(x_ui)) = [150000,64] f32
// ---------------------------------------------------------------------------
extern "C" void kernel_launch(void* const* d_in, const int* in_sizes, int n_in,
                              void* d_out, int out_size)
{
    const int*   uidx = (const int*)d_in[0];
    const int*   iidx = (const int*)d_in[1];
    const int*   ei   = (const int*)d_in[2];
    const float* ut   = (const float*)d_in[5];
    const float* et   = (const float*)d_in[6];
    const float* W    = (const float*)d_in[7];
    float* out = (float*)d_out;
    const int E = in_sizes[2] / 2;

    cudaMemsetAsync(d_out, 0, (size_t)out_size * sizeof(float));
    build_y_kernel<<<1184, 256>>>(uidx, iidx, ut, et, W);
    edge_kernel<<<1184, 256>>>(ei, E, out);
    finalize_kernel<<<1184, 256>>>(out, out_size);
}

// round 3
// speedup vs baseline: 1.1148x; 1.1148x over previous
#include <cuda_runtime.h>
#include <cstddef>

#define N_USERS 50000
#define N_ENT   100000
#define N_TOT   150000
#define D       64
#define E_CAP   1536000

// ---------------------------------------------------------------------------
// Scratch (device globals: no allocation allowed)
// ---------------------------------------------------------------------------
__device__ __align__(256) float g_y[(size_t)N_TOT * D];   // x @ W
__device__ float g_Z;
__device__ int g_deg[N_TOT];
__device__ int g_off[N_TOT + 1];
__device__ int g_cur[N_TOT];
__device__ int g_src_sorted[E_CAP];
__device__ int g_part[1024];

static const int NB_SCAN = (N_TOT + 255) / 256;   // 586

// ---------------------------------------------------------------------------
// init: zero degree histogram + Z
// ---------------------------------------------------------------------------
__global__ void init_kernel() {
    int i = blockIdx.x * blockDim.x + threadIdx.x;
    if (i == 0) g_Z = 0.0f;
    for (; i < N_TOT; i += gridDim.x * blockDim.x) g_deg[i] = 0;
}

// ---------------------------------------------------------------------------
// Pass 1: y = x @ W. Tile = 128 rows, block = 256 threads.
// Each thread computes 8 rows x 4 cols. Per k: 1 LDS.128 (W) + 2 LDS.128 (x)
// for 32 FMAs.
// ---------------------------------------------------------------------------
__global__ void __launch_bounds__(256) build_y_kernel(
    const int* __restrict__ uidx, const int* __restrict__ iidx,
    const float* __restrict__ ut, const float* __restrict__ et,
    const float* __restrict__ W)
{
    __shared__ float Ws[64 * 64];       // 16 KB
    __shared__ float xst[64][128];      // 32 KB, transposed: xst[k][row-in-tile]

    const int tid = threadIdx.x;
    for (int i = tid; i < 1024; i += 256)
        ((float4*)Ws)[i] = ((const float4*)W)[i];

    const int row0 = blockIdx.x * 128;

    // cooperative transposed load: 2 threads per row, 8 float4 each
    {
        const int lr = tid >> 1;          // 0..127 row-in-tile
        const int lj = tid & 1;           // half of the 16 float4s
        const int r  = row0 + lr;
        if (r < N_TOT) {
            const float* xrow;
            if (r < N_USERS) xrow = ut + (size_t)__ldg(uidx + r) * D;
            else             xrow = et + (size_t)__ldg(iidx + (r - N_USERS)) * D;
            #pragma unroll
            for (int i = 0; i < 8; i++) {
                const int c4 = lj * 8 + i;
                float4 v = ((const float4*)xrow)[c4];
                xst[c4 * 4 + 0][lr] = v.x;
                xst[c4 * 4 + 1][lr] = v.y;
                xst[c4 * 4 + 2][lr] = v.z;
                xst[c4 * 4 + 3][lr] = v.w;
            }
        }
    }
    __syncthreads();

    const int j  = tid & 15;   // cols [4j, 4j+4)
    const int rt = tid >> 4;   // rows [8rt, 8rt+8) in tile

    float4 acc[8];
    #pragma unroll
    for (int r = 0; r < 8; r++) acc[r] = make_float4(0.f, 0.f, 0.f, 0.f);

    #pragma unroll 4
    for (int k = 0; k < 64; k++) {
        const float4 w  = *(const float4*)&Ws[k * 64 + j * 4];
        const float4 xa = *(const float4*)&xst[k][rt * 8];
        const float4 xb = *(const float4*)&xst[k][rt * 8 + 4];
        acc[0].x += xa.x * w.x; acc[0].y += xa.x * w.y; acc[0].z += xa.x * w.z; acc[0].w += xa.x * w.w;
        acc[1].x += xa.y * w.x; acc[1].y += xa.y * w.y; acc[1].z += xa.y * w.z; acc[1].w += xa.y * w.w;
        acc[2].x += xa.z * w.x; acc[2].y += xa.z * w.y; acc[2].z += xa.z * w.z; acc[2].w += xa.z * w.w;
        acc[3].x += xa.w * w.x; acc[3].y += xa.w * w.y; acc[3].z += xa.w * w.z; acc[3].w += xa.w * w.w;
        acc[4].x += xb.x * w.x; acc[4].y += xb.x * w.y; acc[4].z += xb.x * w.z; acc[4].w += xb.x * w.w;
        acc[5].x += xb.y * w.x; acc[5].y += xb.y * w.y; acc[5].z += xb.y * w.z; acc[5].w += xb.y * w.w;
        acc[6].x += xb.z * w.x; acc[6].y += xb.z * w.y; acc[6].z += xb.z * w.z; acc[6].w += xb.z * w.w;
        acc[7].x += xb.w * w.x; acc[7].y += xb.w * w.y; acc[7].z += xb.w * w.z; acc[7].w += xb.w * w.w;
    }

    #pragma unroll
    for (int r = 0; r < 8; r++) {
        const int row = row0 + rt * 8 + r;
        if (row < N_TOT)
            ((float4*)(g_y + (size_t)row * D))[j] = acc[r];
    }
}

// ---------------------------------------------------------------------------
// Counting sort by dst: hist -> 3-pass scan -> scatter
// ---------------------------------------------------------------------------
__global__ void hist_kernel(const int* __restrict__ ei, int E) {
    for (int e = blockIdx.x * blockDim.x + threadIdx.x; e < E;
         e += gridDim.x * blockDim.x)
        atomicAdd(&g_deg[__ldg(ei + E + e)], 1);
}

__global__ void __launch_bounds__(256) scan_reduce_kernel() {
    __shared__ int s[256];
    const int t = threadIdx.x;
    const int idx = blockIdx.x * 256 + t;
    int v = (idx < N_TOT) ? g_deg[idx] : 0;
    s[t] = v; __syncthreads();
    for (int o = 128; o > 0; o >>= 1) {
        if (t < o) s[t] += s[t + o];
        __syncthreads();
    }
    if (t == 0) g_part[blockIdx.x] = s[0];
}

__global__ void __launch_bounds__(1024) scan_mid_kernel(int nb) {
    __shared__ int s[1024];
    const int t = threadIdx.x;
    int v = (t < nb) ? g_part[t] : 0;
    s[t] = v; __syncthreads();
    #pragma unroll
    for (int o = 1; o < 1024; o <<= 1) {
        int x = (t >= o) ? s[t - o] : 0;
        __syncthreads();
        s[t] += x;
        __syncthreads();
    }
    g_part[t] = s[t] - v;   // exclusive
}

__global__ void __launch_bounds__(256) scan_final_kernel() {
    __shared__ int s[256];
    const int t = threadIdx.x;
    const int idx = blockIdx.x * 256 + t;
    int v = (idx < N_TOT) ? g_deg[idx] : 0;
    s[t] = v; __syncthreads();
    for (int o = 1; o < 256; o <<= 1) {
        int x = (t >= o) ? s[t - o] : 0;
        __syncthreads();
        s[t] += x;
        __syncthreads();
    }
    const int off = g_part[blockIdx.x] + s[t] - v;   // exclusive prefix
    if (idx < N_TOT) {
        g_off[idx] = off;
        g_cur[idx] = off;
        if (idx == N_TOT - 1) g_off[N_TOT] = off + v;
    }
}

__global__ void scatter_kernel(const int* __restrict__ ei, int E) {
    for (int e = blockIdx.x * blockDim.x + threadIdx.x; e < E;
         e += gridDim.x * blockDim.x) {
        const int d = __ldg(ei + E + e);
        const int s = __ldg(ei + e);
        const int pos = atomicAdd(&g_cur[d], 1);
        g_src_sorted[pos] = s;
    }
}

// ---------------------------------------------------------------------------
// Pass 2 (CSR): ONE FULL WARP per dst node. All 32 lanes share the same loop
// bound -> full-mask shuffles are convergent (this fixes the R2 deadlock).
// Each lane owns 2 floats (float2) of the 64-wide row.
// ---------------------------------------------------------------------------
__global__ void __launch_bounds__(256) edge_csr_kernel(float* __restrict__ out)
{
    const int lane = threadIdx.x & 31;
    const int wid  = (blockIdx.x * blockDim.x + threadIdx.x) >> 5;
    const int nw   = (gridDim.x * blockDim.x) >> 5;

    float zloc = 0.0f;

    for (int d = wid; d < N_TOT; d += nw) {
        const float2 yd = *(const float2*)(g_y + (size_t)d * D + lane * 2);
        const int beg = g_off[d];
        const int end = g_off[d + 1];

        float2 acc = make_float2(0.f, 0.f);
        int s_next = (beg < end) ? __ldg(g_src_sorted + beg) : 0;
        for (int i = beg; i < end; i++) {
            const int s = s_next;
            if (i + 1 < end) s_next = __ldg(g_src_sorted + i + 1);
            const float2 ys = *(const float2*)(g_y + (size_t)s * D + lane * 2);
            float t = ys.x * yd.x + ys.y * yd.y;
            t += __shfl_xor_sync(0xffffffffu, t, 16);
            t += __shfl_xor_sync(0xffffffffu, t, 8);
            t += __shfl_xor_sync(0xffffffffu, t, 4);
            t += __shfl_xor_sync(0xffffffffu, t, 2);
            t += __shfl_xor_sync(0xffffffffu, t, 1);
            const float l = t >= 0.f ? t : 0.2f * t;   // leaky_relu(0.2)
            const float p = __expf(l);                 // logits O(1): no max-shift
            if (lane == 0) zloc += p;
            acc.x += p * ys.x; acc.y += p * ys.y;
        }
        *(float2*)(out + (size_t)d * D + lane * 2) = acc;
    }

    // block-reduce zloc -> one atomic per block (convergent: loop is done)
    float z = zloc;
    #pragma unroll
    for (int o = 16; o > 0; o >>= 1) z += __shfl_xor_sync(0xffffffffu, z, o);
    __shared__ float sz[8];
    if (lane == 0) sz[threadIdx.x >> 5] = z;
    __syncthreads();
    if (threadIdx.x == 0) {
        float s = 0.f;
        #pragma unroll
        for (int w = 0; w < 8; w++) s += sz[w];
        atomicAdd(&g_Z, s);
    }
}

// ---------------------------------------------------------------------------
// Pass 3: out = relu(out) / Z   (relu(a/Z) == relu(a)/Z since Z > 0)
// ---------------------------------------------------------------------------
__global__ void __launch_bounds__(256) finalize_kernel(float* __restrict__ out, int n)
{
    const float invZ = 1.0f / g_Z;
    const int n4 = n >> 2;
    float4* o4 = (float4*)out;
    const int st = gridDim.x * blockDim.x;
    for (int i = blockIdx.x * blockDim.x + threadIdx.x; i < n4; i += st) {
        float4 v = o4[i];
        v.x = v.x > 0.f ? v.x * invZ : 0.f;
        v.y = v.y > 0.f ? v.y * invZ : 0.f;
        v.z = v.z > 0.f ? v.z * invZ : 0.f;
        v.w = v.w > 0.f ? v.w * invZ : 0.f;
        o4[i] = v;
    }
}

// ---------------------------------------------------------------------------
// Inputs: 0 user_idx, 1 item_idx, 2 edge_index_ui, (3,4,8 dead), 5 user_table,
// 6 entity_table, 7 W. Output: relu(kgat_ui) [150000,64] f32.
// ---------------------------------------------------------------------------
extern "C" void kernel_launch(void* const* d_in, const int* in_sizes, int n_in,
                              void* d_out, int out_size)
{
    const int*   uidx = (const int*)d_in[0];
    const int*   iidx = (const int*)d_in[1];
    const int*   ei   = (const int*)d_in[2];
    const float* ut   = (const float*)d_in[5];
    const float* et   = (const float*)d_in[6];
    const float* W    = (const float*)d_in[7];
    float* out = (float*)d_out;
    const int E = in_sizes[2] / 2;

    init_kernel<<<160, 256>>>();
    build_y_kernel<<<(N_TOT + 127) / 128, 256>>>(uidx, iidx, ut, et, W);
    hist_kernel<<<1184, 256>>>(ei, E);
    scan_reduce_kernel<<<NB_SCAN, 256>>>();
    scan_mid_kernel<<<1, 1024>>>(NB_SCAN);
    scan_final_kernel<<<NB_SCAN, 256>>>();
    scatter_kernel<<<1184, 256>>>(ei, E);
    edge_csr_kernel<<<1184, 256>>>(out);
    finalize_kernel<<<1184, 256>>>(out, out_size);
}

// round 4
// speedup vs baseline: 1.2424x; 1.1145x over previous
#include <cuda_runtime.h>
#include <cstddef>

#define N_USERS 50000
#define N_ENT   100000
#define N_TOT   150000
#define D       64
#define E_CAP   1536000

// ---------------------------------------------------------------------------
// Scratch (device globals: no allocation allowed)
// ---------------------------------------------------------------------------
__device__ __align__(256) float g_y[(size_t)N_TOT * D];   // x @ W
__device__ float g_Z;
__device__ int g_deg[N_TOT];
__device__ int g_off[N_TOT + 1];
__device__ int g_cur[N_TOT];
__device__ int g_src_sorted[E_CAP];
__device__ int g_part[1024];

static const int NB_SCAN = (N_TOT + 255) / 256;   // 586

// ---------------------------------------------------------------------------
// sort branch step 0: zero degree histogram + Z
// ---------------------------------------------------------------------------
__global__ void init_deg_kernel() {
    int i = blockIdx.x * blockDim.x + threadIdx.x;
    if (i == 0) g_Z = 0.0f;
    int4 z4 = make_int4(0, 0, 0, 0);
    for (int j = i; j < N_TOT / 4; j += gridDim.x * blockDim.x)
        ((int4*)g_deg)[j] = z4;
}

// ---------------------------------------------------------------------------
// build branch: y = x @ W. Tile = 128 rows, block = 256 threads.
// Each thread: 8 rows x 4 cols; per k: 3 LDS.128 for 32 FMAs.
// ---------------------------------------------------------------------------
__global__ void __launch_bounds__(256) build_y_kernel(
    const int* __restrict__ uidx, const int* __restrict__ iidx,
    const float* __restrict__ ut, const float* __restrict__ et,
    const float* __restrict__ W)
{
    __shared__ float Ws[64 * 64];       // 16 KB
    __shared__ float xst[64][128];      // 32 KB, transposed

    const int tid = threadIdx.x;
    for (int i = tid; i < 1024; i += 256)
        ((float4*)Ws)[i] = ((const float4*)W)[i];

    const int row0 = blockIdx.x * 128;
    {
        const int lr = tid >> 1;
        const int lj = tid & 1;
        const int r  = row0 + lr;
        if (r < N_TOT) {
            const float* xrow;
            if (r < N_USERS) xrow = ut + (size_t)__ldg(uidx + r) * D;
            else             xrow = et + (size_t)__ldg(iidx + (r - N_USERS)) * D;
            #pragma unroll
            for (int i = 0; i < 8; i++) {
                const int c4 = lj * 8 + i;
                float4 v = ((const float4*)xrow)[c4];
                xst[c4 * 4 + 0][lr] = v.x;
                xst[c4 * 4 + 1][lr] = v.y;
                xst[c4 * 4 + 2][lr] = v.z;
                xst[c4 * 4 + 3][lr] = v.w;
            }
        }
    }
    __syncthreads();

    const int j  = tid & 15;
    const int rt = tid >> 4;

    float4 acc[8];
    #pragma unroll
    for (int r = 0; r < 8; r++) acc[r] = make_float4(0.f, 0.f, 0.f, 0.f);

    #pragma unroll 4
    for (int k = 0; k < 64; k++) {
        const float4 w  = *(const float4*)&Ws[k * 64 + j * 4];
        const float4 xa = *(const float4*)&xst[k][rt * 8];
        const float4 xb = *(const float4*)&xst[k][rt * 8 + 4];
        acc[0].x += xa.x * w.x; acc[0].y += xa.x * w.y; acc[0].z += xa.x * w.z; acc[0].w += xa.x * w.w;
        acc[1].x += xa.y * w.x; acc[1].y += xa.y * w.y; acc[1].z += xa.y * w.z; acc[1].w += xa.y * w.w;
        acc[2].x += xa.z * w.x; acc[2].y += xa.z * w.y; acc[2].z += xa.z * w.z; acc[2].w += xa.z * w.w;
        acc[3].x += xa.w * w.x; acc[3].y += xa.w * w.y; acc[3].z += xa.w * w.z; acc[3].w += xa.w * w.w;
        acc[4].x += xb.x * w.x; acc[4].y += xb.x * w.y; acc[4].z += xb.x * w.z; acc[4].w += xb.x * w.w;
        acc[5].x += xb.y * w.x; acc[5].y += xb.y * w.y; acc[5].z += xb.y * w.z; acc[5].w += xb.y * w.w;
        acc[6].x += xb.z * w.x; acc[6].y += xb.z * w.y; acc[6].z += xb.z * w.z; acc[6].w += xb.z * w.w;
        acc[7].x += xb.w * w.x; acc[7].y += xb.w * w.y; acc[7].z += xb.w * w.z; acc[7].w += xb.w * w.w;
    }

    #pragma unroll
    for (int r = 0; r < 8; r++) {
        const int row = row0 + rt * 8 + r;
        if (row < N_TOT)
            ((float4*)(g_y + (size_t)row * D))[j] = acc[r];
    }
}

// ---------------------------------------------------------------------------
// Counting sort by dst: hist (int4) -> reduce -> fused scan -> scatter (int4)
// ---------------------------------------------------------------------------
__global__ void hist_kernel(const int* __restrict__ ei, int E) {
    const int n4 = E >> 2;
    const int st = gridDim.x * blockDim.x;
    const int4* d4 = (const int4*)(ei + E);
    for (int i = blockIdx.x * blockDim.x + threadIdx.x; i < n4; i += st) {
        int4 d = __ldg(d4 + i);
        atomicAdd(&g_deg[d.x], 1); atomicAdd(&g_deg[d.y], 1);
        atomicAdd(&g_deg[d.z], 1); atomicAdd(&g_deg[d.w], 1);
    }
    for (int e = (n4 << 2) + blockIdx.x * blockDim.x + threadIdx.x; e < E; e += st)
        atomicAdd(&g_deg[__ldg(ei + E + e)], 1);
}

__global__ void __launch_bounds__(256) scan_reduce_kernel() {
    const int t = threadIdx.x;
    const int idx = blockIdx.x * 256 + t;
    int v = (idx < N_TOT) ? g_deg[idx] : 0;
    #pragma unroll
    for (int o = 16; o > 0; o >>= 1) v += __shfl_xor_sync(0xffffffffu, v, o);
    __shared__ int sw[8];
    if ((t & 31) == 0) sw[t >> 5] = v;
    __syncthreads();
    if (t == 0) {
        int s = 0;
        #pragma unroll
        for (int w = 0; w < 8; w++) s += sw[w];
        g_part[blockIdx.x] = s;
    }
}

// fused mid+final scan: each block redundantly reduces partials < blockIdx
__global__ void __launch_bounds__(256) scan_final_kernel(int nb) {
    __shared__ int s[256];
    __shared__ int sbase;
    const int t = threadIdx.x;
    const int b = blockIdx.x;

    // base = sum of g_part[j] for j < b
    int acc = 0;
    for (int j = t; j < b; j += 256) acc += g_part[j];
    #pragma unroll
    for (int o = 16; o > 0; o >>= 1) acc += __shfl_xor_sync(0xffffffffu, acc, o);
    __shared__ int sw[8];
    if ((t & 31) == 0) sw[t >> 5] = acc;
    __syncthreads();
    if (t == 0) {
        int ss = 0;
        #pragma unroll
        for (int w = 0; w < 8; w++) ss += sw[w];
        sbase = ss;
    }

    const int idx = b * 256 + t;
    int v = (idx < N_TOT) ? g_deg[idx] : 0;
    s[t] = v; __syncthreads();
    #pragma unroll
    for (int o = 1; o < 256; o <<= 1) {
        int x = (t >= o) ? s[t - o] : 0;
        __syncthreads();
        s[t] += x;
        __syncthreads();
    }
    const int off = sbase + s[t] - v;   // exclusive prefix
    if (idx < N_TOT) {
        g_off[idx] = off;
        g_cur[idx] = off;
        if (idx == N_TOT - 1) g_off[N_TOT] = off + v;
    }
}

__global__ void scatter_kernel(const int* __restrict__ ei, int E) {
    const int n4 = E >> 2;
    const int st = gridDim.x * blockDim.x;
    const int4* s4p = (const int4*)ei;
    const int4* d4p = (const int4*)(ei + E);
    for (int i = blockIdx.x * blockDim.x + threadIdx.x; i < n4; i += st) {
        int4 sv = __ldg(s4p + i);
        int4 dv = __ldg(d4p + i);
        g_src_sorted[atomicAdd(&g_cur[dv.x], 1)] = sv.x;
        g_src_sorted[atomicAdd(&g_cur[dv.y], 1)] = sv.y;
        g_src_sorted[atomicAdd(&g_cur[dv.z], 1)] = sv.z;
        g_src_sorted[atomicAdd(&g_cur[dv.w], 1)] = sv.w;
    }
    for (int e = (n4 << 2) + blockIdx.x * blockDim.x + threadIdx.x; e < E; e += st) {
        const int d = __ldg(ei + E + e);
        g_src_sorted[atomicAdd(&g_cur[d], 1)] = __ldg(ei + e);
    }
}

// ---------------------------------------------------------------------------
// Edge pass (CSR): 16-lane group per dst (2 nodes per warp), float4 per lane,
// sub-group shuffle masks (halves may diverge safely), 2-edge unroll for ILP.
// ---------------------------------------------------------------------------
__global__ void __launch_bounds__(256) edge_csr_kernel(float* __restrict__ out)
{
    const int lane = threadIdx.x & 31;
    const int li   = lane & 15;
    const int half = lane >> 4;
    const unsigned mask = 0xFFFFu << (half * 16);
    const int gid  = (blockIdx.x * blockDim.x + threadIdx.x) >> 4;
    const int ng   = (gridDim.x * blockDim.x) >> 4;

    float zloc = 0.0f;

    for (int d = gid; d < N_TOT; d += ng) {
        const float4 yd = *(const float4*)(g_y + (size_t)d * D + li * 4);
        const int beg = g_off[d];
        const int end = g_off[d + 1];

        float4 acc = make_float4(0.f, 0.f, 0.f, 0.f);
        int i = beg;
        for (; i + 2 <= end; i += 2) {
            const int s0 = __ldg(g_src_sorted + i);
            const int s1 = __ldg(g_src_sorted + i + 1);
            const float4 a = *(const float4*)(g_y + (size_t)s0 * D + li * 4);
            const float4 b = *(const float4*)(g_y + (size_t)s1 * D + li * 4);
            float t0 = a.x * yd.x + a.y * yd.y + a.z * yd.z + a.w * yd.w;
            float t1 = b.x * yd.x + b.y * yd.y + b.z * yd.z + b.w * yd.w;
            t0 += __shfl_xor_sync(mask, t0, 8);  t1 += __shfl_xor_sync(mask, t1, 8);
            t0 += __shfl_xor_sync(mask, t0, 4);  t1 += __shfl_xor_sync(mask, t1, 4);
            t0 += __shfl_xor_sync(mask, t0, 2);  t1 += __shfl_xor_sync(mask, t1, 2);
            t0 += __shfl_xor_sync(mask, t0, 1);  t1 += __shfl_xor_sync(mask, t1, 1);
            const float p0 = __expf(t0 >= 0.f ? t0 : 0.2f * t0);
            const float p1 = __expf(t1 >= 0.f ? t1 : 0.2f * t1);
            if (li == 0) zloc += p0 + p1;
            acc.x += p0 * a.x + p1 * b.x;
            acc.y += p0 * a.y + p1 * b.y;
            acc.z += p0 * a.z + p1 * b.z;
            acc.w += p0 * a.w + p1 * b.w;
        }
        if (i < end) {
            const int s0 = __ldg(g_src_sorted + i);
            const float4 a = *(const float4*)(g_y + (size_t)s0 * D + li * 4);
            float t0 = a.x * yd.x + a.y * yd.y + a.z * yd.z + a.w * yd.w;
            t0 += __shfl_xor_sync(mask, t0, 8);
            t0 += __shfl_xor_sync(mask, t0, 4);
            t0 += __shfl_xor_sync(mask, t0, 2);
            t0 += __shfl_xor_sync(mask, t0, 1);
            const float p0 = __expf(t0 >= 0.f ? t0 : 0.2f * t0);
            if (li == 0) zloc += p0;
            acc.x += p0 * a.x; acc.y += p0 * a.y;
            acc.z += p0 * a.z; acc.w += p0 * a.w;
        }
        *(float4*)(out + (size_t)d * D + li * 4) = acc;
    }

    // block-reduce zloc (convergent here)
    float z = zloc;
    #pragma unroll
    for (int o = 16; o > 0; o >>= 1) z += __shfl_xor_sync(0xffffffffu, z, o);
    __shared__ float sz[8];
    if (lane == 0) sz[threadIdx.x >> 5] = z;
    __syncthreads();
    if (threadIdx.x == 0) {
        float s = 0.f;
        #pragma unroll
        for (int w = 0; w < 8; w++) s += sz[w];
        atomicAdd(&g_Z, s);
    }
}

// ---------------------------------------------------------------------------
// finalize: out = relu(out) / Z
// ---------------------------------------------------------------------------
__global__ void __launch_bounds__(256) finalize_kernel(float* __restrict__ out, int n)
{
    const float invZ = 1.0f / g_Z;
    const int n4 = n >> 2;
    float4* o4 = (float4*)out;
    const int st = gridDim.x * blockDim.x;
    for (int i = blockIdx.x * blockDim.x + threadIdx.x; i < n4; i += st) {
        float4 v = o4[i];
        v.x = v.x > 0.f ? v.x * invZ : 0.f;
        v.y = v.y > 0.f ? v.y * invZ : 0.f;
        v.z = v.z > 0.f ? v.z * invZ : 0.f;
        v.w = v.w > 0.f ? v.w * invZ : 0.f;
        o4[i] = v;
    }
}

// ---------------------------------------------------------------------------
// Launch: fork-join graph — sort chain (s2) overlaps build_y (stream 0).
// ---------------------------------------------------------------------------
extern "C" void kernel_launch(void* const* d_in, const int* in_sizes, int n_in,
                              void* d_out, int out_size)
{
    const int*   uidx = (const int*)d_in[0];
    const int*   iidx = (const int*)d_in[1];
    const int*   ei   = (const int*)d_in[2];
    const float* ut   = (const float*)d_in[5];
    const float* et   = (const float*)d_in[6];
    const float* W    = (const float*)d_in[7];
    float* out = (float*)d_out;
    const int E = in_sizes[2] / 2;

    static cudaStream_t s2 = nullptr;
    static cudaEvent_t ev_fork = nullptr, ev_join = nullptr;
    if (s2 == nullptr) {
        cudaStreamCreateWithFlags(&s2, cudaStreamNonBlocking);
        cudaEventCreateWithFlags(&ev_fork, cudaEventDisableTiming);
        cudaEventCreateWithFlags(&ev_join, cudaEventDisableTiming);
    }

    // fork: sort chain on s2
    cudaEventRecord(ev_fork, 0);
    cudaStreamWaitEvent(s2, ev_fork, 0);
    init_deg_kernel<<<160, 256, 0, s2>>>();
    hist_kernel<<<592, 256, 0, s2>>>(ei, E);
    scan_reduce_kernel<<<NB_SCAN, 256, 0, s2>>>();
    scan_final_kernel<<<NB_SCAN, 256, 0, s2>>>(NB_SCAN);
    scatter_kernel<<<592, 256, 0, s2>>>(ei, E);
    cudaEventRecord(ev_join, s2);

    // main branch: y = x @ W (FMA-bound, overlaps with sort chain)
    build_y_kernel<<<(N_TOT + 127) / 128, 256>>>(uidx, iidx, ut, et, W);

    // join
    cudaStreamWaitEvent(0, ev_join, 0);
    edge_csr_kernel<<<1184, 256>>>(out);
    finalize_kernel<<<1184, 256>>>(out, out_size);
}